// round 15
// baseline (speedup 1.0000x reference)
#include <cuda_runtime.h>

// Problem shape (fixed by the bench)
#define BB 8
#define SS 2048
#define HH 2048

// Scratch (no allocations allowed)
__device__ __align__(16) float g_uv[BB * SS * 4];  // per-row dots
__device__ __align__(16) float g_v[BB * SS];       // per-input-position weight
__device__ __align__(16) int   g_seg_start[BB * SS];  // first input s for output row t
__device__ __align__(16) int   g_seg_len[BB * SS];    // inputs per output row t (0 for t>=new_len)
__device__ int   g_new_len[BB];

// ---------------------------------------------------------------------------
// Kernel A v5: thread tid owns h columns tid*4..tid*4+3 (16 W floats in regs).
// All 4 row-loads of the tile are issued UPFRONT (MLP=4 per thread), then
// FFMA + STS.128 per row; one barrier; LDS.128 tail reduce (once per tile).
// ---------------------------------------------------------------------------
__global__ void __launch_bounds__(512, 2) k_dots(const float* __restrict__ h,
                                                 const float* __restrict__ W) {
    const int tid = threadIdx.x;
    const float4* Wp = reinterpret_cast<const float4*>(W);   // W: [2H,2] row-major

    const float4 wa0 = __ldg(Wp + tid * 2 + 0);
    const float4 wa1 = __ldg(Wp + tid * 2 + 1);
    const float4 wb0 = __ldg(Wp + 1024 + tid * 2 + 0);
    const float4 wb1 = __ldg(Wp + 1024 + tid * 2 + 1);

    __shared__ float part[4][512][4];                        // 32KB

    const int row0 = blockIdx.x * 4;
    const float4* hp = reinterpret_cast<const float4*>(h) + (size_t)row0 * (HH / 4);

    // 4 independent loads in flight before any consumer
    float4 hv[4];
    hv[0] = __ldg(hp + tid);
    hv[1] = __ldg(hp + 512 + tid);
    hv[2] = __ldg(hp + 1024 + tid);
    hv[3] = __ldg(hp + 1536 + tid);

#pragma unroll
    for (int rr = 0; rr < 4; rr++) {
        const float4 x = hv[rr];
        const float a0 = x.x * wa0.x + x.y * wa0.z + x.z * wa1.x + x.w * wa1.z;
        const float a1 = x.x * wa0.y + x.y * wa0.w + x.z * wa1.y + x.w * wa1.w;
        const float c0 = x.x * wb0.x + x.y * wb0.z + x.z * wb1.x + x.w * wb1.z;
        const float c1 = x.x * wb0.y + x.y * wb0.w + x.z * wb1.y + x.w * wb1.w;
        *reinterpret_cast<float4*>(&part[rr][tid][0]) = make_float4(a0, a1, c0, c1);
    }
    __syncthreads();                                         // ONE barrier per tile

    // warp w (0..3) reduces row w with LDS.128 + 5-level shuffle.
    const int w = tid >> 5, l = tid & 31;
    if (w < 4) {
        float4 acc = make_float4(0.f, 0.f, 0.f, 0.f);
#pragma unroll
        for (int k = 0; k < 16; k++) {
            const float4 p = *reinterpret_cast<const float4*>(&part[w][l + 32 * k][0]);
            acc.x += p.x; acc.y += p.y; acc.z += p.z; acc.w += p.w;
        }
#pragma unroll
        for (int off = 16; off > 0; off >>= 1) {
            acc.x += __shfl_down_sync(0xffffffffu, acc.x, off);
            acc.y += __shfl_down_sync(0xffffffffu, acc.y, off);
            acc.z += __shfl_down_sync(0xffffffffu, acc.z, off);
            acc.w += __shfl_down_sync(0xffffffffu, acc.w, off);
        }
        if (l == 0)
            *reinterpret_cast<float4*>(&g_uv[(size_t)(row0 + w) * 4]) = acc;
    }
}

// ---------------------------------------------------------------------------
// Kernel P: per-position work, chip-wide parallel: logits, gumbel-softmax, mm.
// ---------------------------------------------------------------------------
__global__ void __launch_bounds__(256) k_point(const int* __restrict__ amask,
                                               const int* __restrict__ smask,
                                               const float* __restrict__ gum,
                                               const float* __restrict__ bias,
                                               float* __restrict__ out) {
    const int sg = blockIdx.x * 256 + threadIdx.x;           // 0..BB*SS-1
    const int s = sg & (SS - 1);

    float* out_mm     = out + (size_t)BB * SS * HH + (size_t)3 * BB * SS;
    float* out_logits = out_mm + (size_t)BB * SS * 2;

    const float b0v = __ldg(bias + 0), b1v = __ldg(bias + 1);

    float l0, l1;
    if (s < SS - 1) {
        const float4 uvA = *reinterpret_cast<const float4*>(&g_uv[(size_t)sg * 4]);
        const float4 uvB = *reinterpret_cast<const float4*>(&g_uv[(size_t)(sg + 1) * 4]);
        l0 = uvA.x + uvB.z + b0v;
        l1 = uvA.y + uvB.w + b1v;
    } else {                                                 // zero stub row
        l0 = b0v; l1 = b1v;
    }
    out_logits[(size_t)sg * 2 + 0] = l0;
    out_logits[(size_t)sg * 2 + 1] = l1;

    const float z0 = l0 + gum[(size_t)sg * 2 + 0];
    const float z1 = l1 + gum[(size_t)sg * 2 + 1];
    const float m = fmaxf(z0, z1);
    const float e0 = expf(z0 - m), e1 = expf(z1 - m);
    const float inv = 1.f / (e0 + e1);
    const float ys0 = e0 * inv, ys1 = e1 * inv;
    const int idx1 = (ys1 > ys0) ? 1 : 0;                    // argmax, ties -> 0
    float mm0 = ((idx1 == 0 ? 1.f : 0.f) - ys0) + ys0;       // straight-through, exact fp order
    float mm1 = ((idx1 == 1 ? 1.f : 0.f) - ys1) + ys1;
    if (smask[sg]) { mm0 = 1.f; mm1 = 0.f; }
    const float mf = amask[sg] ? 1.f : 0.f;
    mm0 *= mf; mm1 *= mf;
    out_mm[(size_t)sg * 2 + 0] = mm0;
    out_mm[(size_t)sg * 2 + 1] = mm1;
}

// ---------------------------------------------------------------------------
// Kernel B3: per-batch serial part, minimal barriers. Computes T, want, v,
// the prefix scan of inc (warp-0 shuffle scan), segment map, small outputs.
// ---------------------------------------------------------------------------
__global__ void __launch_bounds__(256) k_scan2(const int* __restrict__ amask,
                                               float* __restrict__ out) {
    const int b = blockIdx.x;
    const int tid = threadIdx.x;
    const size_t base = (size_t)b * SS;

    __shared__ unsigned char want_sh[SS];
    __shared__ int r_sh[SS];
    __shared__ int part[256];
    __shared__ int cnt_sh[SS];
    __shared__ int sst_sh[SS];
    __shared__ int sh_T;

    float* out_mask    = out + (size_t)BB * SS * HH;
    float* out_special = out_mask + (size_t)BB * SS;
    float* out_counts  = out_special + (size_t)BB * SS;
    const float* out_mm = out_counts + (size_t)BB * SS;

    // --- T: thread partials + warp-0 reduce (2 barriers) ---
    {
        int local = 0;
#pragma unroll
        for (int i = 0; i < 8; i++) local += amask[base + tid * 8 + i];
        part[tid] = local;
    }
    __syncthreads();
    if (tid < 32) {
        int s = 0;
#pragma unroll
        for (int i = 0; i < 8; i++) s += part[tid * 8 + i];
#pragma unroll
        for (int off = 16; off > 0; off >>= 1) s += __shfl_down_sync(0xffffffffu, s, off);
        if (tid == 0) sh_T = s;
    }
    __syncthreads();
    const int T = sh_T;

    // --- want + v from out_mm (4 float4 loads per thread) ---
#pragma unroll
    for (int q = 0; q < 4; q++) {
        const float4 mm2 = *reinterpret_cast<const float4*>(
            out_mm + (base + tid * 8) * 2 + q * 4);          // positions tid*8+2q, +1
        const int s0 = tid * 8 + q * 2;
        const bool w0 = (mm2.y > 0.5f) && (s0 >= 1) && (s0 < T - 1);
        const bool w1 = (mm2.w > 0.5f) && (s0 + 1 >= 1) && (s0 + 1 < T - 1);
        want_sh[s0]     = w0 ? 1 : 0;
        want_sh[s0 + 1] = w1 ? 1 : 0;
        float v0 = w0 ? mm2.y : mm2.x;
        float v1 = w1 ? mm2.w : mm2.z;
        if (s0 == 0) v0 = 1.f;
        if (s0 >= T) v0 = 0.f;
        if (s0 + 1 >= T) v1 = 0.f;
        g_v[base + s0]     = v0;
        g_v[base + s0 + 1] = v1;
    }
    __syncthreads();

    // --- inc + scan: thread partials, warp-0 shuffle scan (2 barriers) ---
    int incs[8];
    {
        int csum = 0;
#pragma unroll
        for (int i = 0; i < 8; i++) {
            const int s = tid * 8 + i;
            const int w = want_sh[s];
            const int wp = (s > 0) ? want_sh[s - 1] : 0;
            const int inc = (s < T && s >= 1 && !(w && wp)) ? 1 : 0;
            csum += inc;
            incs[i] = csum;                          // local inclusive
        }
        part[tid] = csum;
    }
    __syncthreads();
    if (tid < 32) {
        int vals[8];
        int tot = 0;
#pragma unroll
        for (int i = 0; i < 8; i++) { tot += part[tid * 8 + i]; vals[i] = tot; }
        int sc = tot;
#pragma unroll
        for (int off = 1; off < 32; off <<= 1) {
            const int n = __shfl_up_sync(0xffffffffu, sc, off);
            if (tid >= off) sc += n;
        }
        const int excl = sc - tot;
#pragma unroll
        for (int i = 0; i < 8; i++) part[tid * 8 + i] = excl + vals[i];
    }
    __syncthreads();
    {
        const int offset = (tid > 0) ? part[tid - 1] : 0;
#pragma unroll
        for (int i = 0; i < 8; i++) r_sh[tid * 8 + i] = offset + incs[i];
    }

    // --- segment map via shared atomics ---
#pragma unroll
    for (int i = 0; i < 8; i++) { cnt_sh[tid * 8 + i] = 0; sst_sh[tid * 8 + i] = 0x7fffffff; }
    __syncthreads();
#pragma unroll
    for (int i = 0; i < 8; i++) {
        const int s = tid * 8 + i;
        if (s < T) {
            const int r = r_sh[s];
            atomicAdd(&cnt_sh[r], 1);
            atomicMin(&sst_sh[r], s);
        }
    }
    __syncthreads();

    const int nl = r_sh[SS - 1] + 1;                 // matches reference r[:, -1] + 1
#pragma unroll
    for (int i = 0; i < 8; i++) {
        const int t = tid * 8 + i;
        out_mask[base + t]    = (t < nl) ? 1.f : 0.f;
        out_special[base + t] = (t == 0 || t == nl - 1) ? 1.f : 0.f;
        out_counts[base + t]  = (float)cnt_sh[t];
        g_seg_start[base + t] = sst_sh[t];
        g_seg_len[base + t]   = cnt_sh[t];   // 0 for t >= nl
    }
    if (tid == 0) g_new_len[b] = nl;
}

// ---------------------------------------------------------------------------
// Kernel C v4: WARP-PER-ROW, zero barriers. Each warp independently owns one
// output row; lane covers 16 float4s in two halves of 8 (8 independent
// LDG.128 in flight per lane, accs capped at 32 regs). ln==0 rows short-
// circuit to a zero store. Descending traversal + __stcs stores kept.
// ---------------------------------------------------------------------------
__global__ void __launch_bounds__(256, 4) k_merge(const float* __restrict__ h,
                                                  float* __restrict__ out) {
    const int nb = BB * SS / 8;
    const int t0 = ((nb - 1) - blockIdx.x) * 8;      // descending traversal
    const int w = threadIdx.x >> 5;
    const int lane = threadIdx.x & 31;
    const int row = t0 + w;                          // this warp's output row
    const int b = row >> 11;
    const size_t base = (size_t)b * SS;
    const float4* hb = reinterpret_cast<const float4*>(h);
    float4* orow = reinterpret_cast<float4*>(out) + (size_t)row * (HH / 4);

    const int st = g_seg_start[row];                 // warp-uniform (broadcast)
    const int ln = g_seg_len[row];

    if (ln == 0) {                                   // t >= new_len: zeros
        const float4 z = make_float4(0.f, 0.f, 0.f, 0.f);
#pragma unroll
        for (int k = 0; k < 16; k++) __stcs(orow + lane + 32 * k, z);
        return;
    }

    const float v0 = __ldg(g_v + base + st);
    const float4* hr0 = hb + (base + st) * (HH / 4);

#pragma unroll
    for (int half = 0; half < 2; half++) {
        const int off = half * 256 + lane;
        float4 acc[8];
#pragma unroll
        for (int k = 0; k < 8; k++) {                // 8 loads in flight
            const float4 x = __ldg(hr0 + off + 32 * k);
            acc[k] = make_float4(v0 * x.x, v0 * x.y, v0 * x.z, v0 * x.w);
        }
        for (int i = 1; i < ln; i++) {               // uncommon leftovers
            const float wv = __ldg(g_v + base + st + i);
            const float4* hri = hb + (base + st + i) * (HH / 4);
#pragma unroll
            for (int k = 0; k < 8; k++) {
                const float4 x = __ldg(hri + off + 32 * k);
                acc[k].x += wv * x.x; acc[k].y += wv * x.y;
                acc[k].z += wv * x.z; acc[k].w += wv * x.w;
            }
        }
#pragma unroll
        for (int k = 0; k < 8; k++) __stcs(orow + off + 32 * k, acc[k]);
    }
}

// ---------------------------------------------------------------------------
extern "C" void kernel_launch(void* const* d_in, const int* in_sizes, int n_in,
                              void* d_out, int out_size) {
    const float* h     = (const float*)d_in[0];   // [B,S,H] f32
    const int*   amask = (const int*)d_in[1];     // [B,S]   i32
    const int*   smask = (const int*)d_in[2];     // [B,S]   i32
    const float* gum   = (const float*)d_in[3];   // [B,S,2] f32
    const float* W     = (const float*)d_in[4];   // [2H,2]  f32
    const float* bias  = (const float*)d_in[5];   // [2]     f32
    float* out = (float*)d_out;

    k_dots<<<(BB * SS) / 4, 512>>>(h, W);
    k_point<<<(BB * SS) / 256, 256>>>(amask, smask, gum, bias, out);
    k_scan2<<<BB, 256>>>(amask, out);
    k_merge<<<(BB * SS) / 8, 256>>>(h, out);
}

// round 16
// speedup vs baseline: 1.2496x; 1.2496x over previous
#include <cuda_runtime.h>

// Problem shape (fixed by the bench)
#define BB 8
#define SS 2048
#define HH 2048

// Scratch (no allocations allowed)
__device__ __align__(16) float g_uv[BB * SS * 4];  // per-row dots
__device__ __align__(16) float g_v[BB * SS];       // per-input-position weight
__device__ __align__(16) int   g_seg_start[BB * SS];  // first input s for output row t
__device__ __align__(16) int   g_seg_len[BB * SS];    // inputs per output row t (0 for t>=new_len)
__device__ int   g_new_len[BB];

// ---------------------------------------------------------------------------
// Kernel A v5: thread tid owns h columns tid*4..tid*4+3 (16 W floats in regs).
// All 4 row-loads of the tile are issued UPFRONT (MLP=4 per thread), then
// FFMA + STS.128 per row; one barrier; LDS.128 tail reduce (once per tile).
// ---------------------------------------------------------------------------
__global__ void __launch_bounds__(512, 2) k_dots(const float* __restrict__ h,
                                                 const float* __restrict__ W) {
    const int tid = threadIdx.x;
    const float4* Wp = reinterpret_cast<const float4*>(W);   // W: [2H,2] row-major

    const float4 wa0 = __ldg(Wp + tid * 2 + 0);
    const float4 wa1 = __ldg(Wp + tid * 2 + 1);
    const float4 wb0 = __ldg(Wp + 1024 + tid * 2 + 0);
    const float4 wb1 = __ldg(Wp + 1024 + tid * 2 + 1);

    __shared__ float part[4][512][4];                        // 32KB

    const int row0 = blockIdx.x * 4;
    const float4* hp = reinterpret_cast<const float4*>(h) + (size_t)row0 * (HH / 4);

    // 4 independent loads in flight before any consumer
    float4 hv[4];
    hv[0] = __ldg(hp + tid);
    hv[1] = __ldg(hp + 512 + tid);
    hv[2] = __ldg(hp + 1024 + tid);
    hv[3] = __ldg(hp + 1536 + tid);

#pragma unroll
    for (int rr = 0; rr < 4; rr++) {
        const float4 x = hv[rr];
        const float a0 = x.x * wa0.x + x.y * wa0.z + x.z * wa1.x + x.w * wa1.z;
        const float a1 = x.x * wa0.y + x.y * wa0.w + x.z * wa1.y + x.w * wa1.w;
        const float c0 = x.x * wb0.x + x.y * wb0.z + x.z * wb1.x + x.w * wb1.z;
        const float c1 = x.x * wb0.y + x.y * wb0.w + x.z * wb1.y + x.w * wb1.w;
        *reinterpret_cast<float4*>(&part[rr][tid][0]) = make_float4(a0, a1, c0, c1);
    }
    __syncthreads();                                         // ONE barrier per tile

    // warp w (0..3) reduces row w with LDS.128 + 5-level shuffle.
    const int w = tid >> 5, l = tid & 31;
    if (w < 4) {
        float4 acc = make_float4(0.f, 0.f, 0.f, 0.f);
#pragma unroll
        for (int k = 0; k < 16; k++) {
            const float4 p = *reinterpret_cast<const float4*>(&part[w][l + 32 * k][0]);
            acc.x += p.x; acc.y += p.y; acc.z += p.z; acc.w += p.w;
        }
#pragma unroll
        for (int off = 16; off > 0; off >>= 1) {
            acc.x += __shfl_down_sync(0xffffffffu, acc.x, off);
            acc.y += __shfl_down_sync(0xffffffffu, acc.y, off);
            acc.z += __shfl_down_sync(0xffffffffu, acc.z, off);
            acc.w += __shfl_down_sync(0xffffffffu, acc.w, off);
        }
        if (l == 0)
            *reinterpret_cast<float4*>(&g_uv[(size_t)(row0 + w) * 4]) = acc;
    }
}

// ---------------------------------------------------------------------------
// Kernel P: per-position work, chip-wide parallel: logits, gumbel-softmax, mm.
// ---------------------------------------------------------------------------
__global__ void __launch_bounds__(256) k_point(const int* __restrict__ amask,
                                               const int* __restrict__ smask,
                                               const float* __restrict__ gum,
                                               const float* __restrict__ bias,
                                               float* __restrict__ out) {
    const int sg = blockIdx.x * 256 + threadIdx.x;           // 0..BB*SS-1
    const int s = sg & (SS - 1);

    float* out_mm     = out + (size_t)BB * SS * HH + (size_t)3 * BB * SS;
    float* out_logits = out_mm + (size_t)BB * SS * 2;

    const float b0v = __ldg(bias + 0), b1v = __ldg(bias + 1);

    float l0, l1;
    if (s < SS - 1) {
        const float4 uvA = *reinterpret_cast<const float4*>(&g_uv[(size_t)sg * 4]);
        const float4 uvB = *reinterpret_cast<const float4*>(&g_uv[(size_t)(sg + 1) * 4]);
        l0 = uvA.x + uvB.z + b0v;
        l1 = uvA.y + uvB.w + b1v;
    } else {                                                 // zero stub row
        l0 = b0v; l1 = b1v;
    }
    out_logits[(size_t)sg * 2 + 0] = l0;
    out_logits[(size_t)sg * 2 + 1] = l1;

    const float z0 = l0 + gum[(size_t)sg * 2 + 0];
    const float z1 = l1 + gum[(size_t)sg * 2 + 1];
    const float m = fmaxf(z0, z1);
    const float e0 = expf(z0 - m), e1 = expf(z1 - m);
    const float inv = 1.f / (e0 + e1);
    const float ys0 = e0 * inv, ys1 = e1 * inv;
    const int idx1 = (ys1 > ys0) ? 1 : 0;                    // argmax, ties -> 0
    float mm0 = ((idx1 == 0 ? 1.f : 0.f) - ys0) + ys0;       // straight-through, exact fp order
    float mm1 = ((idx1 == 1 ? 1.f : 0.f) - ys1) + ys1;
    if (smask[sg]) { mm0 = 1.f; mm1 = 0.f; }
    const float mf = amask[sg] ? 1.f : 0.f;
    mm0 *= mf; mm1 *= mf;
    out_mm[(size_t)sg * 2 + 0] = mm0;
    out_mm[(size_t)sg * 2 + 1] = mm1;
}

// ---------------------------------------------------------------------------
// Kernel B3: per-batch serial part, minimal barriers. Computes T, want, v,
// the prefix scan of inc (warp-0 shuffle scan), segment map, small outputs.
// ---------------------------------------------------------------------------
__global__ void __launch_bounds__(256) k_scan2(const int* __restrict__ amask,
                                               float* __restrict__ out) {
    const int b = blockIdx.x;
    const int tid = threadIdx.x;
    const size_t base = (size_t)b * SS;

    __shared__ unsigned char want_sh[SS];
    __shared__ int r_sh[SS];
    __shared__ int part[256];
    __shared__ int cnt_sh[SS];
    __shared__ int sst_sh[SS];
    __shared__ int sh_T;

    float* out_mask    = out + (size_t)BB * SS * HH;
    float* out_special = out_mask + (size_t)BB * SS;
    float* out_counts  = out_special + (size_t)BB * SS;
    const float* out_mm = out_counts + (size_t)BB * SS;

    // --- T: thread partials + warp-0 reduce (2 barriers) ---
    {
        int local = 0;
#pragma unroll
        for (int i = 0; i < 8; i++) local += amask[base + tid * 8 + i];
        part[tid] = local;
    }
    __syncthreads();
    if (tid < 32) {
        int s = 0;
#pragma unroll
        for (int i = 0; i < 8; i++) s += part[tid * 8 + i];
#pragma unroll
        for (int off = 16; off > 0; off >>= 1) s += __shfl_down_sync(0xffffffffu, s, off);
        if (tid == 0) sh_T = s;
    }
    __syncthreads();
    const int T = sh_T;

    // --- want + v from out_mm (4 float4 loads per thread) ---
#pragma unroll
    for (int q = 0; q < 4; q++) {
        const float4 mm2 = *reinterpret_cast<const float4*>(
            out_mm + (base + tid * 8) * 2 + q * 4);          // positions tid*8+2q, +1
        const int s0 = tid * 8 + q * 2;
        const bool w0 = (mm2.y > 0.5f) && (s0 >= 1) && (s0 < T - 1);
        const bool w1 = (mm2.w > 0.5f) && (s0 + 1 >= 1) && (s0 + 1 < T - 1);
        want_sh[s0]     = w0 ? 1 : 0;
        want_sh[s0 + 1] = w1 ? 1 : 0;
        float v0 = w0 ? mm2.y : mm2.x;
        float v1 = w1 ? mm2.w : mm2.z;
        if (s0 == 0) v0 = 1.f;
        if (s0 >= T) v0 = 0.f;
        if (s0 + 1 >= T) v1 = 0.f;
        g_v[base + s0]     = v0;
        g_v[base + s0 + 1] = v1;
    }
    __syncthreads();

    // --- inc + scan: thread partials, warp-0 shuffle scan (2 barriers) ---
    int incs[8];
    {
        int csum = 0;
#pragma unroll
        for (int i = 0; i < 8; i++) {
            const int s = tid * 8 + i;
            const int w = want_sh[s];
            const int wp = (s > 0) ? want_sh[s - 1] : 0;
            const int inc = (s < T && s >= 1 && !(w && wp)) ? 1 : 0;
            csum += inc;
            incs[i] = csum;                          // local inclusive
        }
        part[tid] = csum;
    }
    __syncthreads();
    if (tid < 32) {
        int vals[8];
        int tot = 0;
#pragma unroll
        for (int i = 0; i < 8; i++) { tot += part[tid * 8 + i]; vals[i] = tot; }
        int sc = tot;
#pragma unroll
        for (int off = 1; off < 32; off <<= 1) {
            const int n = __shfl_up_sync(0xffffffffu, sc, off);
            if (tid >= off) sc += n;
        }
        const int excl = sc - tot;
#pragma unroll
        for (int i = 0; i < 8; i++) part[tid * 8 + i] = excl + vals[i];
    }
    __syncthreads();
    {
        const int offset = (tid > 0) ? part[tid - 1] : 0;
#pragma unroll
        for (int i = 0; i < 8; i++) r_sh[tid * 8 + i] = offset + incs[i];
    }

    // --- segment map via shared atomics ---
#pragma unroll
    for (int i = 0; i < 8; i++) { cnt_sh[tid * 8 + i] = 0; sst_sh[tid * 8 + i] = 0x7fffffff; }
    __syncthreads();
#pragma unroll
    for (int i = 0; i < 8; i++) {
        const int s = tid * 8 + i;
        if (s < T) {
            const int r = r_sh[s];
            atomicAdd(&cnt_sh[r], 1);
            atomicMin(&sst_sh[r], s);
        }
    }
    __syncthreads();

    const int nl = r_sh[SS - 1] + 1;                 // matches reference r[:, -1] + 1
#pragma unroll
    for (int i = 0; i < 8; i++) {
        const int t = tid * 8 + i;
        out_mask[base + t]    = (t < nl) ? 1.f : 0.f;
        out_special[base + t] = (t == 0 || t == nl - 1) ? 1.f : 0.f;
        out_counts[base + t]  = (float)cnt_sh[t];
        g_seg_start[base + t] = sst_sh[t];
        g_seg_len[base + t]   = cnt_sh[t];   // 0 for t >= nl
    }
    if (tid == 0) g_new_len[b] = nl;
}

// ---------------------------------------------------------------------------
// Kernel C v5: back to the proven 8-rows-per-256-thread-block shape, with
// reg-cheap improvements only:
//   - int4-batched seg metadata + batched first-input v loads (from v3)
//   - rolling ONE-ROW prefetch: next row's two LDG.128 issue before current
//     row's FMA+store (live set ~6 float4 -> high occupancy, MLP~4)
//   - no nl branch: ln==0 gives v0=0 -> zero output through the uniform path
// Descending traversal + __stcs stores kept (L2 reuse of k_dots' stream).
// ---------------------------------------------------------------------------
__global__ void __launch_bounds__(256) k_merge(const float* __restrict__ h,
                                               float* __restrict__ out) {
    const int blk = (BB * SS / 8 - 1) - blockIdx.x;  // descending traversal
    const int t0 = blk * 8;                          // first global output row
    const int b = t0 >> 11;                          // batch (8 rows never straddle)
    const int tid = threadIdx.x;
    const int q0 = tid * 2;
    const size_t base = (size_t)b * SS;
    const float4* hb = reinterpret_cast<const float4*>(h);

    // metadata for 8 rows: 4 wide loads, all independent
    const int4 stA = *reinterpret_cast<const int4*>(&g_seg_start[t0]);
    const int4 stB = *reinterpret_cast<const int4*>(&g_seg_start[t0 + 4]);
    const int4 lnA = *reinterpret_cast<const int4*>(&g_seg_len[t0]);
    const int4 lnB = *reinterpret_cast<const int4*>(&g_seg_len[t0 + 4]);
    int st[8] = {stA.x, stA.y, stA.z, stA.w, stB.x, stB.y, stB.z, stB.w};
    const int ln[8] = {lnA.x, lnA.y, lnA.z, lnA.w, lnB.x, lnB.y, lnB.z, lnB.w};

    // sanitize starts and batch the first-input v loads (v=0 when ln==0)
    float v0[8];
#pragma unroll
    for (int j = 0; j < 8; j++) {
        if (ln[j] == 0) st[j] = 0;                   // safe dummy (weight is 0)
        v0[j] = (ln[j] > 0) ? __ldg(g_v + base + st[j]) : 0.f;
    }

    // rolling prefetch over rows
    float4 c0 = __ldg(hb + (base + st[0]) * (HH / 4) + q0);
    float4 c1 = __ldg(hb + (base + st[0]) * (HH / 4) + q0 + 1);

#pragma unroll
    for (int j = 0; j < 8; j++) {
        float4 n0, n1;
        if (j < 7) {                                 // prefetch next row's first input
            const float4* hn = hb + (base + st[j + 1]) * (HH / 4);
            n0 = __ldg(hn + q0);
            n1 = __ldg(hn + q0 + 1);
        }

        const float v = v0[j];
        float4 acc0 = make_float4(v * c0.x, v * c0.y, v * c0.z, v * c0.w);
        float4 acc1 = make_float4(v * c1.x, v * c1.y, v * c1.z, v * c1.w);

        for (int i = 1; i < ln[j]; i++) {            // uncommon leftovers
            const size_t srow = base + st[j] + i;
            const float wv = __ldg(g_v + srow);
            const float4* hr = hb + srow * (HH / 4);
            const float4 x0 = __ldg(hr + q0);
            const float4 x1 = __ldg(hr + q0 + 1);
            acc0.x += wv * x0.x; acc0.y += wv * x0.y; acc0.z += wv * x0.z; acc0.w += wv * x0.w;
            acc1.x += wv * x1.x; acc1.y += wv * x1.y; acc1.z += wv * x1.z; acc1.w += wv * x1.w;
        }

        float4* orow = reinterpret_cast<float4*>(out) + (size_t)(t0 + j) * (HH / 4);
        __stcs(orow + q0,     acc0);
        __stcs(orow + q0 + 1, acc1);

        if (j < 7) { c0 = n0; c1 = n1; }
    }
}

// ---------------------------------------------------------------------------
extern "C" void kernel_launch(void* const* d_in, const int* in_sizes, int n_in,
                              void* d_out, int out_size) {
    const float* h     = (const float*)d_in[0];   // [B,S,H] f32
    const int*   amask = (const int*)d_in[1];     // [B,S]   i32
    const int*   smask = (const int*)d_in[2];     // [B,S]   i32
    const float* gum   = (const float*)d_in[3];   // [B,S,2] f32
    const float* W     = (const float*)d_in[4];   // [2H,2]  f32
    const float* bias  = (const float*)d_in[5];   // [2]     f32
    float* out = (float*)d_out;

    k_dots<<<(BB * SS) / 4, 512>>>(h, W);
    k_point<<<(BB * SS) / 256, 256>>>(amask, smask, gum, bias, out);
    k_scan2<<<BB, 256>>>(amask, out);
    k_merge<<<(BB * SS) / 8, 256>>>(h, out);
}